// round 12
// baseline (speedup 1.0000x reference)
#include <cuda_runtime.h>
#include <math.h>

// SO3Reparameterize: fused triple-GEMV (65536x1024 @ 1024x9) + Rodrigues epilogue.
// R12: 4 rows/thread (THREADS=64, warp owns 128 rows) -> weight-broadcast LDS
// amortized over 4 rows; one warp/SMSP already saturates the FMA pipe
// (FFMA2 rt_SMSP=2). Warp-autonomous cp.async 3-stage rings, transposed smem
// weights via broadcast LDS.128, fma.rn.f32x2, exact tail wait.

#define D_IN    1024
#define THREADS 64
#define TILE_R  256          // rows per block (2 warps x 128 rows)
#define KC      16           // k-chunk
#define ROWPAD  20           // floats per staged row (conflict-free phases)
#define NCHUNK  (D_IN / KC)  // 64
#define NPAIR   (D_IN / 2)   // 512
#define STAGES  3
#define WROWS   128                                  // rows per warp
#define WARP_FLOATS (WROWS * ROWPAD)                 // 2560 floats = 10240 B
#define XS_FLOATS   (2 * WARP_FLOATS)                // per stage, 2 warps = 20480 B
#define SMEM_BYTES  (9 * NPAIR * 8 + STAGES * XS_FLOATS * 4)   // 36864+61440=98304

typedef unsigned long long u64;

__device__ __forceinline__ u64 pack2(float a, float b) {
    u64 r;
    asm("mov.b64 %0, {%1, %2};" : "=l"(r) : "r"(__float_as_uint(a)), "r"(__float_as_uint(b)));
    return r;
}
__device__ __forceinline__ void unpack2(u64 v, float& a, float& b) {
    unsigned lo, hi;
    asm("mov.b64 {%0, %1}, %2;" : "=r"(lo), "=r"(hi) : "l"(v));
    a = __uint_as_float(lo);
    b = __uint_as_float(hi);
}
__device__ __forceinline__ void ffma2(u64& acc, u64 x, u64 w) {
    asm("fma.rn.f32x2 %0, %1, %2, %0;" : "+l"(acc) : "l"(x), "l"(w));
}
__device__ __forceinline__ void cp_async16(unsigned saddr, const void* gptr) {
    asm volatile("cp.async.cg.shared.global [%0], [%1], 16;" :: "r"(saddr), "l"(gptr));
}
__device__ __forceinline__ void cp_commit() {
    asm volatile("cp.async.commit_group;");
}
__device__ __forceinline__ void cp_wait1() {
    asm volatile("cp.async.wait_group 1;");
}
__device__ __forceinline__ void cp_wait0() {
    asm volatile("cp.async.wait_group 0;");
}

__device__ __forceinline__ void rodrigues(float vx, float vy, float vz, float* R) {
    float th  = sqrtf(vx * vx + vy * vy + vz * vz);
    float inv = 1.0f / th;
    float ux = vx * inv, uy = vy * inv, uz = vz * inv;
    float s = sinf(th), c = cosf(th), C = 1.0f - c;
    R[0] = c + ux * ux * C;      R[1] = ux * uy * C - uz * s;  R[2] = ux * uz * C + uy * s;
    R[3] = uy * ux * C + uz * s; R[4] = c + uy * uy * C;       R[5] = uy * uz * C - ux * s;
    R[6] = uz * ux * C - uy * s; R[7] = uz * uy * C + ux * s;  R[8] = c + uz * uz * C;
}

__device__ __forceinline__ float softplus_stable(float t) {
    return fmaxf(t, 0.0f) + log1pf(expf(-fabsf(t)));
}

__device__ __forceinline__ void epilogue_row(
    int row, int B, int n, const u64* acc,
    const float* __restrict__ bmu, const float* __restrict__ bd,
    const float* __restrict__ bl,
    const float* __restrict__ eps, float* __restrict__ out)
{
    float s[9];
#pragma unroll
    for (int j = 0; j < 9; j++) {
        float lo, hi;
        unpack2(acc[j], lo, hi);
        s[j] = lo + hi;
    }
    float m0 = s[0] + bmu[0], m1 = s[1] + bmu[1], m2 = s[2] + bmu[2];
    float sd0 = sqrtf(softplus_stable(s[3] + bd[0]));
    float sd1 = sqrtf(softplus_stable(s[4] + bd[1]));
    float sd2 = sqrtf(softplus_stable(s[5] + bd[2]));
    float l0 = s[6] + bl[0], l1 = s[7] + bl[1], l2 = s[8] + bl[2];

    float Rm[9];
    rodrigues(m0, m1, m2, Rm);

    for (int jn = 0; jn < n; jn++) {
        size_t base = (size_t)(jn * B + row) * 3;
        float e0 = eps[base + 0], e1 = eps[base + 1], e2 = eps[base + 2];
        float a0 = sd0 * e0, a1 = sd1 * e1, a2 = sd2 * e2;
        float v0 = a0;
        float v1 = l0 * a0 + a1;
        float v2 = l1 * a0 + l2 * a1 + a2;

        float Rv[9];
        rodrigues(v0, v1, v2, Rv);

        float* o = out + (size_t)(jn * B + row) * 9;
#pragma unroll
        for (int i = 0; i < 3; i++) {
#pragma unroll
            for (int k = 0; k < 3; k++) {
                o[i * 3 + k] = Rm[i * 3 + 0] * Rv[0 * 3 + k]
                             + Rm[i * 3 + 1] * Rv[1 * 3 + k]
                             + Rm[i * 3 + 2] * Rv[2 * 3 + k];
            }
        }
    }
}

__global__ void __launch_bounds__(THREADS)
so3_kernel(const float* __restrict__ x, const float* __restrict__ eps,
           const float* __restrict__ Wmu, const float* __restrict__ bmu,
           const float* __restrict__ Wd,  const float* __restrict__ bd,
           const float* __restrict__ Wl,  const float* __restrict__ bl,
           float* __restrict__ out, int B, int n)
{
    extern __shared__ unsigned char smem_raw[];
    u64*   wpkT = (u64*)smem_raw;                         // [j][k2], 9*512 pairs
    float* xs   = (float*)(smem_raw + 9 * NPAIR * 8);     // [STAGES][2 warps][WROWS*ROWPAD]

    const int tid  = threadIdx.x;
    const int w    = tid >> 5;
    const int lane = tid & 31;
    const int row0 = blockIdx.x * TILE_R;

    // Warp w owns rows row0 + w*128 + [0,128); this thread computes rows
    // lane + 32*r, r = 0..3.
    const int rbase = row0 + w * WROWS;

    // Staging map: 128 rows x 4 16B-quarters = 512 segs, 16 per lane.
    // Lane covers rows a + 8i (i=0..15), quarter cf.
    const int a  = lane >> 2;
    const int cf = lane & 3;
    const unsigned sA = (unsigned)(w * WARP_FLOATS * 4 + (a * ROWPAD + cf * 4) * 4);
    int grA = rbase + a;   if (grA > B - 1) grA = B - 1;
    const float* gA = x + (size_t)grA * D_IN + cf * 4;

    const unsigned xs_base = (unsigned)__cvta_generic_to_shared(xs);

    // Prologue cp.async first so loads fly during weight staging.
#pragma unroll
    for (int s = 0; s < STAGES - 1; s++) {
        unsigned base = xs_base + (unsigned)(s * XS_FLOATS * 4);
        const float* pA = gA + s * KC;
#pragma unroll
        for (int i = 0; i < 16; i++)   // rows a + 8i
            cp_async16(base + sA + (unsigned)(i * 8 * ROWPAD * 4),
                       pA + (size_t)(8 * i) * D_IN);
        cp_commit();
    }

    // Stage weights transposed: wpkT[j*NPAIR + k2] = (W[2k2][c], W[2k2+1][c]).
    for (int i = tid; i < 9 * NPAIR; i += THREADS) {
        int j = i / NPAIR, k2 = i - j * NPAIR;
        const float* W;
        int c;
        if (j < 3)      { W = Wmu; c = j; }
        else if (j < 6) { W = Wd;  c = j - 3; }
        else            { W = Wl;  c = j - 6; }
        wpkT[i] = pack2(W[(2 * k2) * 3 + c], W[(2 * k2 + 1) * 3 + c]);
    }
    __syncthreads();   // weights visible; mainloop is barrier-free

    u64 acc[4][9];
#pragma unroll
    for (int r = 0; r < 4; r++)
#pragma unroll
        for (int j = 0; j < 9; j++) acc[r][j] = 0ull;

    int slot  = 0;                // per-warp ring state
    int pslot = STAGES - 1;

#pragma unroll 1
    for (int ch = 0; ch < NCHUNK; ch++) {
        // Exact wait: chunk ch complete. At the final chunk its group is the
        // newest -> drain fully (tail-race fix from R8).
        if (ch < NCHUNK - 1) cp_wait1(); else cp_wait0();
        __syncwarp();

        if (ch + STAGES - 1 < NCHUNK) {
            unsigned base = xs_base + (unsigned)(pslot * XS_FLOATS * 4);
            const float* pA = gA + (ch + STAGES - 1) * KC;
#pragma unroll
            for (int i = 0; i < 16; i++)
                cp_async16(base + sA + (unsigned)(i * 8 * ROWPAD * 4),
                           pA + (size_t)(8 * i) * D_IN);
            cp_commit();
        }

        // Compute chunk ch for 4 rows from this warp's partition.
        const float* x0 = xs + slot * XS_FLOATS + w * WARP_FLOATS + lane * ROWPAD;
        const u64*   wch = wpkT + ch * (KC / 2);
#pragma unroll
        for (int p = 0; p < KC / 4; p++) {                 // 4 quads
            ulonglong2 xv[4];
#pragma unroll
            for (int r = 0; r < 4; r++)
                xv[r] = *(const ulonglong2*)&x0[r * 32 * ROWPAD + p * 4];
#pragma unroll
            for (int j = 0; j < 9; j++) {
                ulonglong2 wv = *(const ulonglong2*)&wch[j * NPAIR + 2 * p];  // broadcast
#pragma unroll
                for (int r = 0; r < 4; r++) {
                    ffma2(acc[r][j], xv[r].x, wv.x);
                    ffma2(acc[r][j], xv[r].y, wv.y);
                }
            }
        }

        slot  = (slot  + 1 == STAGES) ? 0 : slot  + 1;
        pslot = (pslot + 1 == STAGES) ? 0 : pslot + 1;
    }

#pragma unroll 1
    for (int r = 0; r < 4; r++) {
        int row = rbase + 32 * r + lane;
        if (row < B)
            epilogue_row(row, B, n, acc[r], bmu, bd, bl, eps, out);
    }
}

extern "C" void kernel_launch(void* const* d_in, const int* in_sizes, int n_in,
                              void* d_out, int out_size)
{
    const float* x   = (const float*)d_in[0];
    const float* eps = (const float*)d_in[1];
    const float* Wmu = (const float*)d_in[2];
    const float* bmu = (const float*)d_in[3];
    const float* Wd  = (const float*)d_in[4];
    const float* bd  = (const float*)d_in[5];
    const float* Wl  = (const float*)d_in[6];
    const float* bl  = (const float*)d_in[7];

    const int B = in_sizes[0] / D_IN;
    const int n = in_sizes[1] / (B * 3);

    cudaFuncSetAttribute(so3_kernel, cudaFuncAttributeMaxDynamicSharedMemorySize, SMEM_BYTES);

    const int grid = (B + TILE_R - 1) / TILE_R;
    so3_kernel<<<grid, THREADS, SMEM_BYTES>>>(x, eps, Wmu, bmu, Wd, bd, Wl, bl,
                                              (float*)d_out, B, n);
}

// round 13
// speedup vs baseline: 1.5221x; 1.5221x over previous
#include <cuda_runtime.h>
#include <math.h>

// SO3Reparameterize: fused triple-GEMV (65536x1024 @ 1024x9) + Rodrigues epilogue.
// R13: R7 operating point (2 rows/thread, 8 warps/SM, warp-autonomous cp.async
// rings) with a deeper pipeline: ROWPAD=16 + XOR swizzle shrinks staging so
// STAGES=4 fits at 2 blocks/SM; prefetch is issued BEFORE the wait; graded
// tail waits (3/2/1/0) keep the exact-wait fix.

#define D_IN    1024
#define THREADS 128
#define TILE_R  256          // rows per block (2 per thread)
#define KC      16           // k-chunk
#define NCHUNK  (D_IN / KC)  // 64
#define NPAIR   (D_IN / 2)   // 512
#define STAGES  4
#define WROWS   64                                   // rows per warp
#define WARP_BYTES  (WROWS * KC * 4)                 // 4096 B per warp per stage
#define XS_BYTES    (4 * WARP_BYTES)                 // 16384 B per stage
#define SMEM_BYTES  (9 * NPAIR * 8 + STAGES * XS_BYTES)   // 36864+65536=102400

typedef unsigned long long u64;

__device__ __forceinline__ u64 pack2(float a, float b) {
    u64 r;
    asm("mov.b64 %0, {%1, %2};" : "=l"(r) : "r"(__float_as_uint(a)), "r"(__float_as_uint(b)));
    return r;
}
__device__ __forceinline__ void unpack2(u64 v, float& a, float& b) {
    unsigned lo, hi;
    asm("mov.b64 {%0, %1}, %2;" : "=r"(lo), "=r"(hi) : "l"(v));
    a = __uint_as_float(lo);
    b = __uint_as_float(hi);
}
__device__ __forceinline__ void ffma2(u64& acc, u64 x, u64 w) {
    asm("fma.rn.f32x2 %0, %1, %2, %0;" : "+l"(acc) : "l"(x), "l"(w));
}
__device__ __forceinline__ void cp_async16(unsigned saddr, const void* gptr) {
    asm volatile("cp.async.cg.shared.global [%0], [%1], 16;" :: "r"(saddr), "l"(gptr));
}
__device__ __forceinline__ void cp_commit() {
    asm volatile("cp.async.commit_group;");
}
__device__ __forceinline__ void cp_wait3() { asm volatile("cp.async.wait_group 3;"); }
__device__ __forceinline__ void cp_wait2() { asm volatile("cp.async.wait_group 2;"); }
__device__ __forceinline__ void cp_wait1() { asm volatile("cp.async.wait_group 1;"); }
__device__ __forceinline__ void cp_wait0() { asm volatile("cp.async.wait_group 0;"); }

__device__ __forceinline__ void rodrigues(float vx, float vy, float vz, float* R) {
    float th  = sqrtf(vx * vx + vy * vy + vz * vz);
    float inv = 1.0f / th;
    float ux = vx * inv, uy = vy * inv, uz = vz * inv;
    float s = sinf(th), c = cosf(th), C = 1.0f - c;
    R[0] = c + ux * ux * C;      R[1] = ux * uy * C - uz * s;  R[2] = ux * uz * C + uy * s;
    R[3] = uy * ux * C + uz * s; R[4] = c + uy * uy * C;       R[5] = uy * uz * C - ux * s;
    R[6] = uz * ux * C - uy * s; R[7] = uz * uy * C + ux * s;  R[8] = c + uz * uz * C;
}

__device__ __forceinline__ float softplus_stable(float t) {
    return fmaxf(t, 0.0f) + log1pf(expf(-fabsf(t)));
}

__device__ __forceinline__ void epilogue_row(
    int row, int B, int n, const u64* acc,
    const float* __restrict__ bmu, const float* __restrict__ bd,
    const float* __restrict__ bl,
    const float* __restrict__ eps, float* __restrict__ out)
{
    float s[9];
#pragma unroll
    for (int j = 0; j < 9; j++) {
        float lo, hi;
        unpack2(acc[j], lo, hi);
        s[j] = lo + hi;
    }
    float m0 = s[0] + bmu[0], m1 = s[1] + bmu[1], m2 = s[2] + bmu[2];
    float sd0 = sqrtf(softplus_stable(s[3] + bd[0]));
    float sd1 = sqrtf(softplus_stable(s[4] + bd[1]));
    float sd2 = sqrtf(softplus_stable(s[5] + bd[2]));
    float l0 = s[6] + bl[0], l1 = s[7] + bl[1], l2 = s[8] + bl[2];

    float Rm[9];
    rodrigues(m0, m1, m2, Rm);

    for (int jn = 0; jn < n; jn++) {
        size_t base = (size_t)(jn * B + row) * 3;
        float e0 = eps[base + 0], e1 = eps[base + 1], e2 = eps[base + 2];
        float a0 = sd0 * e0, a1 = sd1 * e1, a2 = sd2 * e2;
        float v0 = a0;
        float v1 = l0 * a0 + a1;
        float v2 = l1 * a0 + l2 * a1 + a2;

        float Rv[9];
        rodrigues(v0, v1, v2, Rv);

        float* o = out + (size_t)(jn * B + row) * 9;
#pragma unroll
        for (int i = 0; i < 3; i++) {
#pragma unroll
            for (int k = 0; k < 3; k++) {
                o[i * 3 + k] = Rm[i * 3 + 0] * Rv[0 * 3 + k]
                             + Rm[i * 3 + 1] * Rv[1 * 3 + k]
                             + Rm[i * 3 + 2] * Rv[2 * 3 + k];
            }
        }
    }
}

__global__ void __launch_bounds__(THREADS)
so3_kernel(const float* __restrict__ x, const float* __restrict__ eps,
           const float* __restrict__ Wmu, const float* __restrict__ bmu,
           const float* __restrict__ Wd,  const float* __restrict__ bd,
           const float* __restrict__ Wl,  const float* __restrict__ bl,
           float* __restrict__ out, int B, int n)
{
    extern __shared__ unsigned char smem_raw[];
    u64*   wpkT = (u64*)smem_raw;                           // [j][k2], 9*512 pairs
    unsigned char* xs = smem_raw + 9 * NPAIR * 8;           // [STAGES][4 warps][64 rows][64B]

    const int tid  = threadIdx.x;
    const int w    = tid >> 5;
    const int lane = tid & 31;
    const int row0 = blockIdx.x * TILE_R;

    // Warp w owns rows row0 + w*64 + [0,64); this thread computes rows
    // ra = +lane and rb = +lane+32.
    const int ra = row0 + w * 64 + lane;
    const int rb = ra + 32;

    // Staging map: 64 rows x 4 16B-quads; lane covers rows a+8i (i=0..7),
    // logical quad cf, stored at swizzled column scol = cf ^ ((a>>1)&3).
    // Swizzle is invariant under row+8 ((a+8i)>>1 & 3 == (a>>1)&3 + 4i mod 4).
    // Gives a perfect 4-phase (zero-excess-conflict) pattern for stores and
    // for both LDS.128 read rows (lane and lane+32 share (lane>>1)&3).
    const int a    = lane >> 2;
    const int cf   = lane & 3;
    const int scol = cf ^ ((a >> 1) & 3);
    const unsigned sA = (unsigned)(w * WARP_BYTES + a * 64 + scol * 16);
    int grA = row0 + w * 64 + a;   if (grA > B - 1) grA = B - 1;
    const float* gA = x + (size_t)grA * D_IN + cf * 4;

    const unsigned xs_base = (unsigned)__cvta_generic_to_shared(xs);

    // Prologue: issue chunks 0..STAGES-2 into slots 0..STAGES-2 (before weight
    // staging so the loads fly early).
#pragma unroll
    for (int s = 0; s < STAGES - 1; s++) {
        unsigned base = xs_base + (unsigned)(s * XS_BYTES);
        const float* pA = gA + s * KC;
#pragma unroll
        for (int i = 0; i < 8; i++)   // rows a + 8i
            cp_async16(base + sA + (unsigned)(i * 8 * 64), pA + (size_t)(8 * i) * D_IN);
        cp_commit();
    }

    // Stage weights transposed: wpkT[j*NPAIR + k2] = (W[2k2][c], W[2k2+1][c]).
    for (int i = tid; i < 9 * NPAIR; i += THREADS) {
        int j = i / NPAIR, k2 = i - j * NPAIR;
        const float* W;
        int c;
        if (j < 3)      { W = Wmu; c = j; }
        else if (j < 6) { W = Wd;  c = j - 3; }
        else            { W = Wl;  c = j - 6; }
        wpkT[i] = pack2(W[(2 * k2) * 3 + c], W[(2 * k2 + 1) * 3 + c]);
    }
    __syncthreads();   // weights visible; mainloop is barrier-free

    u64 accA[9], accB[9];
#pragma unroll
    for (int j = 0; j < 9; j++) { accA[j] = 0ull; accB[j] = 0ull; }

    // Compute-side swizzle for this thread's rows (lane and lane+32).
    const int sw = (lane >> 1) & 3;
    const unsigned rdA = (unsigned)(w * WARP_BYTES + lane * 64);   // rowA byte base

#pragma unroll 1
    for (int ch = 0; ch < NCHUNK; ch++) {
        // Prefetch chunk ch+STAGES-1 into slot (ch+STAGES-1)&3 (== slot of
        // ch-1, free: its data was consumed last iteration). Issued BEFORE the
        // wait so the new group's LDGSTS don't serialize behind it.
        if (ch + STAGES - 1 < NCHUNK) {
            unsigned base = xs_base + (unsigned)(((ch + STAGES - 1) & 3) * XS_BYTES);
            const float* pA = gA + (ch + STAGES - 1) * KC;
#pragma unroll
            for (int i = 0; i < 8; i++)
                cp_async16(base + sA + (unsigned)(i * 8 * 64), pA + (size_t)(8 * i) * D_IN);
            cp_commit();
        }

        // Graded wait: chunk ch's group must complete. Steady state leaves the
        // 3 newer groups pending; tail tightens 3 -> 2 -> 1 -> 0 (exact tail
        // wait -- the R8 race fix generalized to depth 4).
        {
            int rem = NCHUNK - 1 - ch;
            if (rem >= 3)      cp_wait3();
            else if (rem == 2) cp_wait2();
            else if (rem == 1) cp_wait1();
            else               cp_wait0();
        }
        __syncwarp();

        // Compute chunk ch for both rows from this warp's partition.
        const unsigned char* part = xs + (ch & 3) * XS_BYTES;
        const u64* wch = wpkT + ch * (KC / 2);
#pragma unroll
        for (int p = 0; p < KC / 4; p++) {                 // 4 quads, logical order
            unsigned col = (unsigned)((p ^ sw) * 16);      // swizzled byte column
            ulonglong2 xav = *(const ulonglong2*)(part + rdA + col);
            ulonglong2 xbv = *(const ulonglong2*)(part + rdA + 32 * 64 + col);
#pragma unroll
            for (int j = 0; j < 9; j++) {
                ulonglong2 wv = *(const ulonglong2*)&wch[j * NPAIR + 2 * p];  // broadcast
                ffma2(accA[j], xav.x, wv.x);
                ffma2(accB[j], xbv.x, wv.x);
                ffma2(accA[j], xav.y, wv.y);
                ffma2(accB[j], xbv.y, wv.y);
            }
        }
    }

    if (ra < B) epilogue_row(ra, B, n, accA, bmu, bd, bl, eps, out);
    if (rb < B) epilogue_row(rb, B, n, accB, bmu, bd, bl, eps, out);
}

extern "C" void kernel_launch(void* const* d_in, const int* in_sizes, int n_in,
                              void* d_out, int out_size)
{
    const float* x   = (const float*)d_in[0];
    const float* eps = (const float*)d_in[1];
    const float* Wmu = (const float*)d_in[2];
    const float* bmu = (const float*)d_in[3];
    const float* Wd  = (const float*)d_in[4];
    const float* bd  = (const float*)d_in[5];
    const float* Wl  = (const float*)d_in[6];
    const float* bl  = (const float*)d_in[7];

    const int B = in_sizes[0] / D_IN;
    const int n = in_sizes[1] / (B * 3);

    cudaFuncSetAttribute(so3_kernel, cudaFuncAttributeMaxDynamicSharedMemorySize, SMEM_BYTES);

    const int grid = (B + TILE_R - 1) / TILE_R;
    so3_kernel<<<grid, THREADS, SMEM_BYTES>>>(x, eps, Wmu, bmu, Wd, bd, Wl, bl,
                                              (float*)d_out, B, n);
}

// round 15
// speedup vs baseline: 1.6060x; 1.0551x over previous
#include <cuda_runtime.h>
#include <math.h>

// SO3Reparameterize: fused triple-GEMV (65536x1024 @ 1024x9) + Rodrigues epilogue.
// R15 = R14 resubmit (R14 hit an infra flake, never ran):
// R13 + L2::256B prefetch hint on cp.async. Each 64B/row/chunk request pulls
// the 256B neighborhood (chunks ch..ch+3 of that row) into L2 in one
// contiguous DRAM burst: sequential HBM stream + 3/4 of chunk fetches become
// L2 hits. Everything else identical to R13 (2 rows/thread, 4-stage
// warp-autonomous cp.async rings, XOR swizzle, graded tail waits).

#define D_IN    1024
#define THREADS 128
#define TILE_R  256          // rows per block (2 per thread)
#define KC      16           // k-chunk
#define NCHUNK  (D_IN / KC)  // 64
#define NPAIR   (D_IN / 2)   // 512
#define STAGES  4
#define WROWS   64                                   // rows per warp
#define WARP_BYTES  (WROWS * KC * 4)                 // 4096 B per warp per stage
#define XS_BYTES    (4 * WARP_BYTES)                 // 16384 B per stage
#define SMEM_BYTES  (9 * NPAIR * 8 + STAGES * XS_BYTES)   // 36864+65536=102400

typedef unsigned long long u64;

__device__ __forceinline__ u64 pack2(float a, float b) {
    u64 r;
    asm("mov.b64 %0, {%1, %2};" : "=l"(r) : "r"(__float_as_uint(a)), "r"(__float_as_uint(b)));
    return r;
}
__device__ __forceinline__ void unpack2(u64 v, float& a, float& b) {
    unsigned lo, hi;
    asm("mov.b64 {%0, %1}, %2;" : "=r"(lo), "=r"(hi) : "l"(v));
    a = __uint_as_float(lo);
    b = __uint_as_float(hi);
}
__device__ __forceinline__ void ffma2(u64& acc, u64 x, u64 w) {
    asm("fma.rn.f32x2 %0, %1, %2, %0;" : "+l"(acc) : "l"(x), "l"(w));
}
__device__ __forceinline__ void cp_async16(unsigned saddr, const void* gptr) {
    asm volatile("cp.async.cg.shared.global.L2::256B [%0], [%1], 16;"
                 :: "r"(saddr), "l"(gptr));
}
__device__ __forceinline__ void cp_commit() {
    asm volatile("cp.async.commit_group;");
}
__device__ __forceinline__ void cp_wait3() { asm volatile("cp.async.wait_group 3;"); }
__device__ __forceinline__ void cp_wait2() { asm volatile("cp.async.wait_group 2;"); }
__device__ __forceinline__ void cp_wait1() { asm volatile("cp.async.wait_group 1;"); }
__device__ __forceinline__ void cp_wait0() { asm volatile("cp.async.wait_group 0;"); }

__device__ __forceinline__ void rodrigues(float vx, float vy, float vz, float* R) {
    float th  = sqrtf(vx * vx + vy * vy + vz * vz);
    float inv = 1.0f / th;
    float ux = vx * inv, uy = vy * inv, uz = vz * inv;
    float s = sinf(th), c = cosf(th), C = 1.0f - c;
    R[0] = c + ux * ux * C;      R[1] = ux * uy * C - uz * s;  R[2] = ux * uz * C + uy * s;
    R[3] = uy * ux * C + uz * s; R[4] = c + uy * uy * C;       R[5] = uy * uz * C - ux * s;
    R[6] = uz * ux * C - uy * s; R[7] = uz * uy * C + ux * s;  R[8] = c + uz * uz * C;
}

__device__ __forceinline__ float softplus_stable(float t) {
    return fmaxf(t, 0.0f) + log1pf(expf(-fabsf(t)));
}

__device__ __forceinline__ void epilogue_row(
    int row, int B, int n, const u64* acc,
    const float* __restrict__ bmu, const float* __restrict__ bd,
    const float* __restrict__ bl,
    const float* __restrict__ eps, float* __restrict__ out)
{
    float s[9];
#pragma unroll
    for (int j = 0; j < 9; j++) {
        float lo, hi;
        unpack2(acc[j], lo, hi);
        s[j] = lo + hi;
    }
    float m0 = s[0] + bmu[0], m1 = s[1] + bmu[1], m2 = s[2] + bmu[2];
    float sd0 = sqrtf(softplus_stable(s[3] + bd[0]));
    float sd1 = sqrtf(softplus_stable(s[4] + bd[1]));
    float sd2 = sqrtf(softplus_stable(s[5] + bd[2]));
    float l0 = s[6] + bl[0], l1 = s[7] + bl[1], l2 = s[8] + bl[2];

    float Rm[9];
    rodrigues(m0, m1, m2, Rm);

    for (int jn = 0; jn < n; jn++) {
        size_t base = (size_t)(jn * B + row) * 3;
        float e0 = eps[base + 0], e1 = eps[base + 1], e2 = eps[base + 2];
        float a0 = sd0 * e0, a1 = sd1 * e1, a2 = sd2 * e2;
        float v0 = a0;
        float v1 = l0 * a0 + a1;
        float v2 = l1 * a0 + l2 * a1 + a2;

        float Rv[9];
        rodrigues(v0, v1, v2, Rv);

        float* o = out + (size_t)(jn * B + row) * 9;
#pragma unroll
        for (int i = 0; i < 3; i++) {
#pragma unroll
            for (int k = 0; k < 3; k++) {
                o[i * 3 + k] = Rm[i * 3 + 0] * Rv[0 * 3 + k]
                             + Rm[i * 3 + 1] * Rv[1 * 3 + k]
                             + Rm[i * 3 + 2] * Rv[2 * 3 + k];
            }
        }
    }
}

__global__ void __launch_bounds__(THREADS)
so3_kernel(const float* __restrict__ x, const float* __restrict__ eps,
           const float* __restrict__ Wmu, const float* __restrict__ bmu,
           const float* __restrict__ Wd,  const float* __restrict__ bd,
           const float* __restrict__ Wl,  const float* __restrict__ bl,
           float* __restrict__ out, int B, int n)
{
    extern __shared__ unsigned char smem_raw[];
    u64*   wpkT = (u64*)smem_raw;                           // [j][k2], 9*512 pairs
    unsigned char* xs = smem_raw + 9 * NPAIR * 8;           // [STAGES][4 warps][64 rows][64B]

    const int tid  = threadIdx.x;
    const int w    = tid >> 5;
    const int lane = tid & 31;
    const int row0 = blockIdx.x * TILE_R;

    // Warp w owns rows row0 + w*64 + [0,64); this thread computes rows
    // ra = +lane and rb = +lane+32.
    const int ra = row0 + w * 64 + lane;
    const int rb = ra + 32;

    // Staging map: 64 rows x 4 16B-quads; lane covers rows a+8i (i=0..7),
    // logical quad cf, stored at swizzled column scol = cf ^ ((a>>1)&3).
    const int a    = lane >> 2;
    const int cf   = lane & 3;
    const int scol = cf ^ ((a >> 1) & 3);
    const unsigned sA = (unsigned)(w * WARP_BYTES + a * 64 + scol * 16);
    int grA = row0 + w * 64 + a;   if (grA > B - 1) grA = B - 1;
    const float* gA = x + (size_t)grA * D_IN + cf * 4;

    const unsigned xs_base = (unsigned)__cvta_generic_to_shared(xs);

    // Prologue: issue chunks 0..STAGES-2 into slots 0..STAGES-2.
#pragma unroll
    for (int s = 0; s < STAGES - 1; s++) {
        unsigned base = xs_base + (unsigned)(s * XS_BYTES);
        const float* pA = gA + s * KC;
#pragma unroll
        for (int i = 0; i < 8; i++)   // rows a + 8i
            cp_async16(base + sA + (unsigned)(i * 8 * 64), pA + (size_t)(8 * i) * D_IN);
        cp_commit();
    }

    // Stage weights transposed: wpkT[j*NPAIR + k2] = (W[2k2][c], W[2k2+1][c]).
    for (int i = tid; i < 9 * NPAIR; i += THREADS) {
        int j = i / NPAIR, k2 = i - j * NPAIR;
        const float* W;
        int c;
        if (j < 3)      { W = Wmu; c = j; }
        else if (j < 6) { W = Wd;  c = j - 3; }
        else            { W = Wl;  c = j - 6; }
        wpkT[i] = pack2(W[(2 * k2) * 3 + c], W[(2 * k2 + 1) * 3 + c]);
    }
    __syncthreads();   // weights visible; mainloop is barrier-free

    u64 accA[9], accB[9];
#pragma unroll
    for (int j = 0; j < 9; j++) { accA[j] = 0ull; accB[j] = 0ull; }

    // Compute-side swizzle for this thread's rows (lane and lane+32).
    const int sw = (lane >> 1) & 3;
    const unsigned rdA = (unsigned)(w * WARP_BYTES + lane * 64);   // rowA byte base

#pragma unroll 1
    for (int ch = 0; ch < NCHUNK; ch++) {
        // Prefetch chunk ch+STAGES-1 BEFORE the wait (slot of ch-1 is free).
        if (ch + STAGES - 1 < NCHUNK) {
            unsigned base = xs_base + (unsigned)(((ch + STAGES - 1) & 3) * XS_BYTES);
            const float* pA = gA + (ch + STAGES - 1) * KC;
#pragma unroll
            for (int i = 0; i < 8; i++)
                cp_async16(base + sA + (unsigned)(i * 8 * 64), pA + (size_t)(8 * i) * D_IN);
            cp_commit();
        }

        // Graded wait: chunk ch's group must be complete; tail tightens
        // 3 -> 2 -> 1 -> 0 (exact tail wait).
        {
            int rem = NCHUNK - 1 - ch;
            if (rem >= 3)      cp_wait3();
            else if (rem == 2) cp_wait2();
            else if (rem == 1) cp_wait1();
            else               cp_wait0();
        }
        __syncwarp();

        // Compute chunk ch for both rows from this warp's partition.
        const unsigned char* part = xs + (ch & 3) * XS_BYTES;
        const u64* wch = wpkT + ch * (KC / 2);
#pragma unroll
        for (int p = 0; p < KC / 4; p++) {                 // 4 quads, logical order
            unsigned col = (unsigned)((p ^ sw) * 16);      // swizzled byte column
            ulonglong2 xav = *(const ulonglong2*)(part + rdA + col);
            ulonglong2 xbv = *(const ulonglong2*)(part + rdA + 32 * 64 + col);
#pragma unroll
            for (int j = 0; j < 9; j++) {
                ulonglong2 wv = *(const ulonglong2*)&wch[j * NPAIR + 2 * p];  // broadcast
                ffma2(accA[j], xav.x, wv.x);
                ffma2(accB[j], xbv.x, wv.x);
                ffma2(accA[j], xav.y, wv.y);
                ffma2(accB[j], xbv.y, wv.y);
            }
        }
    }

    if (ra < B) epilogue_row(ra, B, n, accA, bmu, bd, bl, eps, out);
    if (rb < B) epilogue_row(rb, B, n, accB, bmu, bd, bl, eps, out);
}

extern "C" void kernel_launch(void* const* d_in, const int* in_sizes, int n_in,
                              void* d_out, int out_size)
{
    const float* x   = (const float*)d_in[0];
    const float* eps = (const float*)d_in[1];
    const float* Wmu = (const float*)d_in[2];
    const float* bmu = (const float*)d_in[3];
    const float* Wd  = (const float*)d_in[4];
    const float* bd  = (const float*)d_in[5];
    const float* Wl  = (const float*)d_in[6];
    const float* bl  = (const float*)d_in[7];

    const int B = in_sizes[0] / D_IN;
    const int n = in_sizes[1] / (B * 3);

    cudaFuncSetAttribute(so3_kernel, cudaFuncAttributeMaxDynamicSharedMemorySize, SMEM_BYTES);

    const int grid = (B + TILE_R - 1) / TILE_R;
    so3_kernel<<<grid, THREADS, SMEM_BYTES>>>(x, eps, Wmu, bmu, Wd, bd, Wl, bl,
                                              (float*)d_out, B, n);
}

// round 16
// speedup vs baseline: 1.6146x; 1.0054x over previous
#include <cuda_runtime.h>
#include <math.h>

// SO3Reparameterize: fused triple-GEMV (65536x1024 @ 1024x9) + Rodrigues epilogue.
// R16 = R15 + paired-chunk compute regions: one wait covers two 16-k chunks,
// doubling the straight-line LDS/FFMA region the compiler can software-
// pipeline and halving wait/branch overhead. Memory stream identical to R15
// (4-stage warp-autonomous cp.async rings, L2::256B, XOR swizzle). Wait grades
// re-derived for the paired structure; prefetchB lands in the slot compute(c0)
// just vacated.

#define D_IN    1024
#define THREADS 128
#define TILE_R  256          // rows per block (2 per thread)
#define KC      16           // k-chunk
#define NCHUNK  (D_IN / KC)  // 64
#define NPAIR   (D_IN / 2)   // 512
#define STAGES  4
#define WROWS   64                                   // rows per warp
#define WARP_BYTES  (WROWS * KC * 4)                 // 4096 B per warp per stage
#define XS_BYTES    (4 * WARP_BYTES)                 // 16384 B per stage
#define SMEM_BYTES  (9 * NPAIR * 8 + STAGES * XS_BYTES)   // 36864+65536=102400

typedef unsigned long long u64;

__device__ __forceinline__ u64 pack2(float a, float b) {
    u64 r;
    asm("mov.b64 %0, {%1, %2};" : "=l"(r) : "r"(__float_as_uint(a)), "r"(__float_as_uint(b)));
    return r;
}
__device__ __forceinline__ void unpack2(u64 v, float& a, float& b) {
    unsigned lo, hi;
    asm("mov.b64 {%0, %1}, %2;" : "=r"(lo), "=r"(hi) : "l"(v));
    a = __uint_as_float(lo);
    b = __uint_as_float(hi);
}
__device__ __forceinline__ void ffma2(u64& acc, u64 x, u64 w) {
    asm("fma.rn.f32x2 %0, %1, %2, %0;" : "+l"(acc) : "l"(x), "l"(w));
}
__device__ __forceinline__ void cp_async16(unsigned saddr, const void* gptr) {
    asm volatile("cp.async.cg.shared.global.L2::256B [%0], [%1], 16;"
                 :: "r"(saddr), "l"(gptr));
}
__device__ __forceinline__ void cp_commit() {
    asm volatile("cp.async.commit_group;");
}
__device__ __forceinline__ void cp_wait3() { asm volatile("cp.async.wait_group 3;"); }
__device__ __forceinline__ void cp_wait2() { asm volatile("cp.async.wait_group 2;"); }
__device__ __forceinline__ void cp_wait1() { asm volatile("cp.async.wait_group 1;"); }
__device__ __forceinline__ void cp_wait0() { asm volatile("cp.async.wait_group 0;"); }

__device__ __forceinline__ void rodrigues(float vx, float vy, float vz, float* R) {
    float th  = sqrtf(vx * vx + vy * vy + vz * vz);
    float inv = 1.0f / th;
    float ux = vx * inv, uy = vy * inv, uz = vz * inv;
    float s = sinf(th), c = cosf(th), C = 1.0f - c;
    R[0] = c + ux * ux * C;      R[1] = ux * uy * C - uz * s;  R[2] = ux * uz * C + uy * s;
    R[3] = uy * ux * C + uz * s; R[4] = c + uy * uy * C;       R[5] = uy * uz * C - ux * s;
    R[6] = uz * ux * C - uy * s; R[7] = uz * uy * C + ux * s;  R[8] = c + uz * uz * C;
}

__device__ __forceinline__ float softplus_stable(float t) {
    return fmaxf(t, 0.0f) + log1pf(expf(-fabsf(t)));
}

__device__ __forceinline__ void epilogue_row(
    int row, int B, int n, const u64* acc,
    const float* __restrict__ bmu, const float* __restrict__ bd,
    const float* __restrict__ bl,
    const float* __restrict__ eps, float* __restrict__ out)
{
    float s[9];
#pragma unroll
    for (int j = 0; j < 9; j++) {
        float lo, hi;
        unpack2(acc[j], lo, hi);
        s[j] = lo + hi;
    }
    float m0 = s[0] + bmu[0], m1 = s[1] + bmu[1], m2 = s[2] + bmu[2];
    float sd0 = sqrtf(softplus_stable(s[3] + bd[0]));
    float sd1 = sqrtf(softplus_stable(s[4] + bd[1]));
    float sd2 = sqrtf(softplus_stable(s[5] + bd[2]));
    float l0 = s[6] + bl[0], l1 = s[7] + bl[1], l2 = s[8] + bl[2];

    float Rm[9];
    rodrigues(m0, m1, m2, Rm);

    for (int jn = 0; jn < n; jn++) {
        size_t base = (size_t)(jn * B + row) * 3;
        float e0 = eps[base + 0], e1 = eps[base + 1], e2 = eps[base + 2];
        float a0 = sd0 * e0, a1 = sd1 * e1, a2 = sd2 * e2;
        float v0 = a0;
        float v1 = l0 * a0 + a1;
        float v2 = l1 * a0 + l2 * a1 + a2;

        float Rv[9];
        rodrigues(v0, v1, v2, Rv);

        float* o = out + (size_t)(jn * B + row) * 9;
#pragma unroll
        for (int i = 0; i < 3; i++) {
#pragma unroll
            for (int k = 0; k < 3; k++) {
                o[i * 3 + k] = Rm[i * 3 + 0] * Rv[0 * 3 + k]
                             + Rm[i * 3 + 1] * Rv[1 * 3 + k]
                             + Rm[i * 3 + 2] * Rv[2 * 3 + k];
            }
        }
    }
}

// One 16-k chunk of dual-row accumulation from a staged smem partition.
__device__ __forceinline__ void compute_chunk(
    const unsigned char* part, const u64* wch,
    unsigned rdA, int sw, u64* accA, u64* accB)
{
#pragma unroll
    for (int p = 0; p < KC / 4; p++) {                 // 4 quads, logical order
        unsigned col = (unsigned)((p ^ sw) * 16);      // swizzled byte column
        ulonglong2 xav = *(const ulonglong2*)(part + rdA + col);
        ulonglong2 xbv = *(const ulonglong2*)(part + rdA + 32 * 64 + col);
#pragma unroll
        for (int j = 0; j < 9; j++) {
            ulonglong2 wv = *(const ulonglong2*)&wch[j * NPAIR + 2 * p];  // broadcast
            ffma2(accA[j], xav.x, wv.x);
            ffma2(accB[j], xbv.x, wv.x);
            ffma2(accA[j], xav.y, wv.y);
            ffma2(accB[j], xbv.y, wv.y);
        }
    }
}

__global__ void __launch_bounds__(THREADS)
so3_kernel(const float* __restrict__ x, const float* __restrict__ eps,
           const float* __restrict__ Wmu, const float* __restrict__ bmu,
           const float* __restrict__ Wd,  const float* __restrict__ bd,
           const float* __restrict__ Wl,  const float* __restrict__ bl,
           float* __restrict__ out, int B, int n)
{
    extern __shared__ unsigned char smem_raw[];
    u64*   wpkT = (u64*)smem_raw;                           // [j][k2], 9*512 pairs
    unsigned char* xs = smem_raw + 9 * NPAIR * 8;           // [STAGES][4 warps][64 rows][64B]

    const int tid  = threadIdx.x;
    const int w    = tid >> 5;
    const int lane = tid & 31;
    const int row0 = blockIdx.x * TILE_R;

    const int ra = row0 + w * 64 + lane;
    const int rb = ra + 32;

    // Staging map: lane covers rows a+8i (i=0..7), logical quad cf, stored at
    // swizzled column scol = cf ^ ((a>>1)&3) (invariant under row+8).
    const int a    = lane >> 2;
    const int cf   = lane & 3;
    const int scol = cf ^ ((a >> 1) & 3);
    const unsigned sA = (unsigned)(w * WARP_BYTES + a * 64 + scol * 16);
    int grA = row0 + w * 64 + a;   if (grA > B - 1) grA = B - 1;
    const float* gA = x + (size_t)grA * D_IN + cf * 4;

    const unsigned xs_base = (unsigned)__cvta_generic_to_shared(xs);

    // Prologue: issue chunks 0..STAGES-2 into slots 0..STAGES-2.
#pragma unroll
    for (int s = 0; s < STAGES - 1; s++) {
        unsigned base = xs_base + (unsigned)(s * XS_BYTES);
        const float* pA = gA + s * KC;
#pragma unroll
        for (int i = 0; i < 8; i++)   // rows a + 8i
            cp_async16(base + sA + (unsigned)(i * 8 * 64), pA + (size_t)(8 * i) * D_IN);
        cp_commit();
    }

    // Stage weights transposed: wpkT[j*NPAIR + k2] = (W[2k2][c], W[2k2+1][c]).
    for (int i = tid; i < 9 * NPAIR; i += THREADS) {
        int j = i / NPAIR, k2 = i - j * NPAIR;
        const float* W;
        int c;
        if (j < 3)      { W = Wmu; c = j; }
        else if (j < 6) { W = Wd;  c = j - 3; }
        else            { W = Wl;  c = j - 6; }
        wpkT[i] = pack2(W[(2 * k2) * 3 + c], W[(2 * k2 + 1) * 3 + c]);
    }
    __syncthreads();   // weights visible; mainloop is barrier-free

    u64 accA[9], accB[9];
#pragma unroll
    for (int j = 0; j < 9; j++) { accA[j] = 0ull; accB[j] = 0ull; }

    const int sw = (lane >> 1) & 3;
    const unsigned rdA = (unsigned)(w * WARP_BYTES + lane * 64);   // rowA byte base

    // Paired mainloop: 32 steps of 2 chunks. Commits happen strictly in chunk
    // order, so before compute(cX) the newest committed group is known and the
    // wait grade is min(3, NCHUNK-1-cX) after the corresponding prefetch.
#pragma unroll 1
    for (int c0 = 0; c0 < NCHUNK; c0 += 2) {
        const int c1 = c0 + 1;

        // prefetchA: chunk c0+3 -> slot (c0+3)&3 (slot of c0-1, consumed last step)
        if (c0 + 3 < NCHUNK) {
            unsigned base = xs_base + (unsigned)(((c0 + 3) & 3) * XS_BYTES);
            const float* pA = gA + (c0 + 3) * KC;
#pragma unroll
            for (int i = 0; i < 8; i++)
                cp_async16(base + sA + (unsigned)(i * 8 * 64), pA + (size_t)(8 * i) * D_IN);
            cp_commit();
        }
        // waitA: chunk c0 complete. Newest committed = min(c0+3, 63).
        // p = 63-c0 is odd: >=3 everywhere except c0=62 -> 1.
        if (NCHUNK - 1 - c0 >= 3) cp_wait3(); else cp_wait1();
        __syncwarp();

        compute_chunk(xs + (c0 & 3) * XS_BYTES, wpkT + c0 * (KC / 2),
                      rdA, sw, accA, accB);

        // prefetchB: chunk c1+3 -> slot (c0+4)&3 == slot of c0, just consumed.
        if (c1 + 3 < NCHUNK) {
            unsigned base = xs_base + (unsigned)(((c1 + 3) & 3) * XS_BYTES);
            const float* pA = gA + (c1 + 3) * KC;
#pragma unroll
            for (int i = 0; i < 8; i++)
                cp_async16(base + sA + (unsigned)(i * 8 * 64), pA + (size_t)(8 * i) * D_IN);
            cp_commit();
        }
        // waitB: chunk c1 complete. q = 62-c0 even: >=3 steady, 2 at c0=60, 0 at 62.
        {
            int q = NCHUNK - 1 - c1;
            if (q >= 3)      cp_wait3();
            else if (q == 2) cp_wait2();
            else             cp_wait0();
        }
        __syncwarp();

        compute_chunk(xs + (c1 & 3) * XS_BYTES, wpkT + c1 * (KC / 2),
                      rdA, sw, accA, accB);
    }

    if (ra < B) epilogue_row(ra, B, n, accA, bmu, bd, bl, eps, out);
    if (rb < B) epilogue_row(rb, B, n, accB, bmu, bd, bl, eps, out);
}

extern "C" void kernel_launch(void* const* d_in, const int* in_sizes, int n_in,
                              void* d_out, int out_size)
{
    const float* x   = (const float*)d_in[0];
    const float* eps = (const float*)d_in[1];
    const float* Wmu = (const float*)d_in[2];
    const float* bmu = (const float*)d_in[3];
    const float* Wd  = (const float*)d_in[4];
    const float* bd  = (const float*)d_in[5];
    const float* Wl  = (const float*)d_in[6];
    const float* bl  = (const float*)d_in[7];

    const int B = in_sizes[0] / D_IN;
    const int n = in_sizes[1] / (B * 3);

    cudaFuncSetAttribute(so3_kernel, cudaFuncAttributeMaxDynamicSharedMemorySize, SMEM_BYTES);

    const int grid = (B + TILE_R - 1) / TILE_R;
    so3_kernel<<<grid, THREADS, SMEM_BYTES>>>(x, eps, Wmu, bmu, Wd, bd, Wl, bl,
                                              (float*)d_out, B, n);
}